// round 8
// baseline (speedup 1.0000x reference)
#include <cuda_runtime.h>
#include <math.h>

#define BT 4096
#define CLIPF 0.2f

// ------------------------------ scratch ------------------------------------
__device__ float  g_feat[BT * 256];
__device__ float  g_xz[BT * 1024];
__device__ float  g_hbuf[2 * 64 * 256];
__device__ float  g_lstm[BT * 256];
__device__ float  g_lg_pir[BT];
__device__ float  g_lg_pim[BT];
__device__ float  g_vpred[BT];
__device__ double g_ent_pir[BT];
__device__ double g_ent_pim[BT];
__device__ double g_vf_row[BT];

__device__ unsigned int          g_bar_cnt = 0u;
__device__ volatile unsigned int g_bar_gen = 0u;

__device__ __forceinline__ void grid_barrier(unsigned int nblocks) {
    __threadfence();
    __syncthreads();
    if (threadIdx.x == 0) {
        unsigned int gen = g_bar_gen;
        if (atomicAdd(&g_bar_cnt, 1u) == nblocks - 1u) {
            g_bar_cnt = 0u;
            __threadfence();
            g_bar_gen = gen + 1u;
        } else {
            while (g_bar_gen == gen) { __nanosleep(40); }
        }
    }
    __syncthreads();
    __threadfence();
}

__device__ __forceinline__ float leaky(float v) { return v > 0.f ? v : 0.2f * v; }
__device__ __forceinline__ float sigm(float v)  { return 1.f / (1.f + expf(-v)); }

// ---- packed f32x2 helpers (sm_103a FFMA2) ----------------------------------
__device__ __forceinline__ unsigned long long pk2(float x, float y) {
    unsigned long long r;
    asm("mov.b64 %0, {%1,%2};" : "=l"(r) : "f"(x), "f"(y));
    return r;
}
__device__ __forceinline__ void upk2(unsigned long long v, float& x, float& y) {
    asm("mov.b64 {%0,%1}, %2;" : "=f"(x), "=f"(y) : "l"(v));
}
__device__ __forceinline__ unsigned long long fma2_(unsigned long long a,
                                                    unsigned long long b,
                                                    unsigned long long c) {
    unsigned long long d;
    asm("fma.rn.f32x2 %0, %1, %2, %3;" : "=l"(d) : "l"(a), "l"(b), "l"(c));
    return d;
}

// ------------------------------ conv stack ---------------------------------
__global__ __launch_bounds__(256) void conv_kernel(
    const float* __restrict__ x,
    const float* __restrict__ W1, const float* __restrict__ b1,
    const float* __restrict__ W2, const float* __restrict__ b2,
    const float* __restrict__ W3, const float* __restrict__ b3,
    const float* __restrict__ W4, const float* __restrict__ b4)
{
    __shared__ float w1[512], w2[2048];
    __shared__ float sb1[16], sb2[32], sb3[64], sb4[128];
    __shared__ float sin_[832], a1[384], a2[480], a3[128];
    const int tid = threadIdx.x;
    for (int i = tid; i < 512;  i += 256) w1[i] = W1[i];
    for (int i = tid; i < 2048; i += 256) w2[i] = W2[i];
    if (tid < 16)  sb1[tid] = b1[tid];
    if (tid < 32)  sb2[tid] = b2[tid];
    if (tid < 64)  sb3[tid] = b3[tid];
    if (tid < 128) sb4[tid] = b4[tid];

    for (int s = 0; s < 8; s++) {
        const int bt = blockIdx.x * 8 + s;
        __syncthreads();
        for (int i = tid; i < 832; i += 256) sin_[i] = x[(size_t)bt * 832 + i];
        __syncthreads();
        for (int o = tid; o < 384; o += 256) {
            int oh = o >> 6, rem = o & 63, ow = rem >> 4, co = rem & 15;
            float acc = sb1[co];
#pragma unroll
            for (int kh = 0; kh < 2; kh++)
#pragma unroll
                for (int kw = 0; kw < 2; kw++)
#pragma unroll
                    for (int ci = 0; ci < 8; ci++)
                        acc = fmaf(sin_[(oh*2+kh)*64 + (ow*2+kw)*8 + ci],
                                   w1[((kh*2+kw)*8 + ci)*16 + co], acc);
            a1[o] = leaky(acc);
        }
        __syncthreads();
        for (int o = tid; o < 480; o += 256) {
            int oh = o / 96, r2 = o % 96, ow = r2 >> 5, co = r2 & 31;
            float acc = sb2[co];
#pragma unroll
            for (int kh = 0; kh < 2; kh++)
#pragma unroll
                for (int kw = 0; kw < 2; kw++)
#pragma unroll
                    for (int ci = 0; ci < 16; ci++)
                        acc = fmaf(a1[(oh+kh)*64 + (ow+kw)*16 + ci],
                                   w2[((kh*2+kw)*16 + ci)*32 + co], acc);
            a2[o] = leaky(acc);
        }
        __syncthreads();
        for (int o = tid; o < 128; o += 256) {
            int oh = o >> 6, co = o & 63;
            float acc = sb3[co];
#pragma unroll
            for (int kh = 0; kh < 2; kh++)
#pragma unroll
                for (int kw = 0; kw < 2; kw++)
#pragma unroll 8
                    for (int ci = 0; ci < 32; ci++)
                        acc = fmaf(a2[(oh*2+kh)*96 + kw*32 + ci],
                                   __ldg(&W3[((kh*2+kw)*32 + ci)*64 + co]), acc);
            a3[o] = leaky(acc);
        }
        __syncthreads();
        {
            int o = tid, oh = o >> 7, co = o & 127;
            float acc = sb4[co];
#pragma unroll 8
            for (int ci = 0; ci < 64; ci++)
                acc = fmaf(a3[oh*64 + ci], __ldg(&W4[ci*128 + co]), acc);
            g_feat[(size_t)bt * 256 + co*2 + oh] = leaky(acc);
        }
    }
}

// ------------------------------ xz = feat @ Wk + b (packed f32x2) -----------
// 256 blocks x 256 threads, 16 rows/block, 1024 cols. Row pairs packed.
__global__ __launch_bounds__(256, 2) void xz_kernel(const float* __restrict__ Wk,
                                                    const float* __restrict__ lb)
{
    __shared__ float aT[256][18];   // transposed activations, pair-aligned
    const int tid = threadIdx.x;
    const int r0 = blockIdx.x * 16;
    for (int i = tid; i < 4096; i += 256) {
        int r = i >> 8, k = i & 255;
        aT[k][r] = g_feat[(size_t)(r0 + r) * 256 + k];
    }
    __syncthreads();

    const int jb = tid * 4;
    unsigned long long acc[8][4];
#pragma unroll
    for (int p = 0; p < 8; p++)
#pragma unroll
        for (int c = 0; c < 4; c++) acc[p][c] = 0ull;

    float4 wnext = __ldg((const float4*)(Wk + jb));
#pragma unroll 1
    for (int k = 0; k < 256; k++) {
        float4 w = wnext;
        if (k < 255) wnext = __ldg((const float4*)(Wk + (size_t)(k + 1) * 1024 + jb));
        unsigned long long w0 = pk2(w.x, w.x), w1 = pk2(w.y, w.y);
        unsigned long long w2 = pk2(w.z, w.z), w3 = pk2(w.w, w.w);
#pragma unroll
        for (int p = 0; p < 8; p++) {
            unsigned long long ap = *(const unsigned long long*)&aT[k][2 * p];
            acc[p][0] = fma2_(ap, w0, acc[p][0]);
            acc[p][1] = fma2_(ap, w1, acc[p][1]);
            acc[p][2] = fma2_(ap, w2, acc[p][2]);
            acc[p][3] = fma2_(ap, w3, acc[p][3]);
        }
    }
    float4 bv = __ldg((const float4*)(lb + jb));
#pragma unroll 1
    for (int p = 0; p < 8; p++) {
        float lo0, hi0, lo1, hi1, lo2, hi2, lo3, hi3;
        upk2(acc[p][0], lo0, hi0); upk2(acc[p][1], lo1, hi1);
        upk2(acc[p][2], lo2, hi2); upk2(acc[p][3], lo3, hi3);
        float4 oA; oA.x = lo0 + bv.x; oA.y = lo1 + bv.y; oA.z = lo2 + bv.z; oA.w = lo3 + bv.w;
        float4 oB; oB.x = hi0 + bv.x; oB.y = hi1 + bv.y; oB.z = hi2 + bv.z; oB.w = hi3 + bv.w;
        *(float4*)&g_xz[(size_t)(r0 + 2 * p) * 1024 + jb]     = oA;
        *(float4*)&g_xz[(size_t)(r0 + 2 * p + 1) * 1024 + jb] = oB;
    }
}

// ------------------------------ LSTM (persistent, packed) -------------------
__global__ __launch_bounds__(256) void lstm_kernel(const float* __restrict__ Wr)
{
    __shared__ float2 wp[4][256];     // (col j0, col j0+1) per gate per k
    __shared__ float z_sm[64][4][2];
    __shared__ float c_sm[64][2];
    const int tid = threadIdx.x;
    const int j0 = blockIdx.x * 2;

    for (int i = tid; i < 2048; i += 256) {
        int u = i & 1, k = (i >> 1) & 255, g = i >> 9;
        ((float*)wp)[(g * 256 + k) * 2 + u] = Wr[(size_t)k * 1024 + g * 256 + j0 + u];
    }
    if (tid < 128) c_sm[tid >> 1][tid & 1] = 0.f;
    __syncthreads();

    const int b = tid >> 2;
    const int g = tid & 3;

    for (int t = 0; t < 64; t++) {
        const size_t row = (size_t)(b * 64 + t);
        unsigned long long acc = pk2(g_xz[row * 1024 + g * 256 + j0],
                                     g_xz[row * 1024 + g * 256 + j0 + 1]);
        if (t > 0) {
            const float* h = g_hbuf + ((t - 1) & 1) * (64 * 256) + b * 256;
            const unsigned long long* w = (const unsigned long long*)wp[g];
#pragma unroll 4
            for (int k = 0; k < 256; k += 4) {
                float4 h4 = __ldcg((const float4*)(h + k));
                acc = fma2_(pk2(h4.x, h4.x), w[k + 0], acc);
                acc = fma2_(pk2(h4.y, h4.y), w[k + 1], acc);
                acc = fma2_(pk2(h4.z, h4.z), w[k + 2], acc);
                acc = fma2_(pk2(h4.w, h4.w), w[k + 3], acc);
            }
        }
        float z0, z1; upk2(acc, z0, z1);
        z_sm[b][g][0] = z0;
        z_sm[b][g][1] = z1;
        __syncthreads();
        if (tid < 128) {
            int b2 = tid >> 1, u = tid & 1;
            float zi = z_sm[b2][0][u], zf = z_sm[b2][1][u];
            float zg = z_sm[b2][2][u], zo = z_sm[b2][3][u];
            float c = sigm(zf) * c_sm[b2][u] + sigm(zi) * tanhf(zg);
            float hv = sigm(zo) * tanhf(c);
            c_sm[b2][u] = c;
            __stcg(&g_hbuf[(t & 1) * (64 * 256) + b2 * 256 + j0 + u], hv);
            g_lstm[(size_t)(b2 * 64 + t) * 256 + j0 + u] = hv;
        }
        grid_barrier(gridDim.x);
    }
}

// ------------------------------ pir head + vpred (smem-staged) ---------------
__global__ __launch_bounds__(256) void pir_v_kernel(
    const float* __restrict__ pirW, const float* __restrict__ pirb,
    const float* __restrict__ vW,  const float* __restrict__ vb,
    const int* __restrict__ a_taken)
{
    __shared__ float ws[256 * 36];
    __shared__ float vws[256];
    __shared__ float hs[8][256];
    const int tid = threadIdx.x, warp = tid >> 5, lane = tid & 31;
    const int r0 = blockIdx.x * 8;

    for (int i = tid; i < 9216; i += 256) ws[i] = pirW[i];
    vws[tid] = vW[tid];
    for (int i = tid; i < 2048; i += 256)
        hs[i >> 8][i & 255] = g_lstm[(size_t)(r0 + (i >> 8)) * 256 + (i & 255)];
    __syncthreads();

    const int i = r0 + warp;
    float acc0 = 0.f, acc1 = 0.f, accv = 0.f;
#pragma unroll 4
    for (int k = 0; k < 256; k++) {
        float hk = hs[warp][k];
        acc0 = fmaf(hk, ws[k * 36 + lane], acc0);
        if (lane < 4) acc1 = fmaf(hk, ws[k * 36 + 32 + lane], acc1);
    }
    for (int k = lane; k < 256; k += 32) accv = fmaf(hs[warp][k], vws[k], accv);

    float l0 = acc0 + __ldg(&pirb[lane]);
    float l1 = (lane < 4) ? acc1 + __ldg(&pirb[lane + 32]) : 0.f;
    float e0 = expf(l0);
    float e1 = (lane < 4) ? expf(l1) : 0.f;
    float cs = e0 + e1;
    float ct = e0 * l0 + ((lane < 4) ? e1 * l1 : 0.f);
#pragma unroll
    for (int o = 16; o > 0; o >>= 1) {
        cs   += __shfl_down_sync(0xffffffffu, cs, o);
        ct   += __shfl_down_sync(0xffffffffu, ct, o);
        accv += __shfl_down_sync(0xffffffffu, accv, o);
    }
    float S = __shfl_sync(0xffffffffu, cs, 0);
    int a = a_taken[i];
    float laA = __shfl_sync(0xffffffffu, l0, a & 31);
    float laB = __shfl_sync(0xffffffffu, l1, a & 31);
    float la = (a < 32) ? laA : laB;
    if (lane == 0) {
        double lS = log((double)S);
        g_ent_pir[i] = (double)ct / (double)S - lS;
        g_lg_pir[i]  = (float)((double)la - lS);
        g_vpred[i]   = accv + vb[0];
    }
}

// ------------------------------ pim GEMM (packed) + fused epilogue -----------
__global__ __launch_bounds__(256, 2) void pim_kernel(
    const float* __restrict__ pimW, const float* __restrict__ pimb,
    const int* __restrict__ mask, const int* __restrict__ a_taken)
{
    __shared__ float aT[256][18];
    __shared__ float redS[16][8], redT[16][8];
    __shared__ double sRun[16], tRun[16];
    __shared__ float la_sm[16];
    __shared__ int aidx[16];
    const int tid = threadIdx.x, lane = tid & 31, warp = tid >> 5;
    const int r0 = blockIdx.x * 16;

    for (int i = tid; i < 4096; i += 256) {
        int r = i >> 8, k = i & 255;
        aT[k][r] = g_lstm[(size_t)(r0 + r) * 256 + k];
    }
    if (tid < 16) { sRun[tid] = 0.0; tRun[tid] = 0.0; aidx[tid] = a_taken[r0 + tid]; la_sm[tid] = 0.f; }
    __syncthreads();

#pragma unroll 1
    for (int tile = 0; tile < 4; tile++) {
        const int jb = tile * 1024 + tid * 4;
        const float* Wp = pimW + jb;
        unsigned long long acc[8][4];
#pragma unroll
        for (int p = 0; p < 8; p++)
#pragma unroll
            for (int c = 0; c < 4; c++) acc[p][c] = 0ull;

        float4 wnext = __ldg((const float4*)Wp);
#pragma unroll 1
        for (int k = 0; k < 256; k++) {
            float4 w = wnext;
            if (k < 255) wnext = __ldg((const float4*)(Wp + (size_t)(k + 1) * 4096));
            unsigned long long w0 = pk2(w.x, w.x), w1 = pk2(w.y, w.y);
            unsigned long long w2 = pk2(w.z, w.z), w3 = pk2(w.w, w.w);
#pragma unroll
            for (int p = 0; p < 8; p++) {
                unsigned long long ap = *(const unsigned long long*)&aT[k][2 * p];
                acc[p][0] = fma2_(ap, w0, acc[p][0]);
                acc[p][1] = fma2_(ap, w1, acc[p][1]);
                acc[p][2] = fma2_(ap, w2, acc[p][2]);
                acc[p][3] = fma2_(ap, w3, acc[p][3]);
            }
        }
        float4 bv = __ldg((const float4*)(pimb + jb));
#pragma unroll 1
        for (int p = 0; p < 8; p++) {
            float v0[2], v1[2], v2[2], v3[2];
            upk2(acc[p][0], v0[0], v0[1]); upk2(acc[p][1], v1[0], v1[1]);
            upk2(acc[p][2], v2[0], v2[1]); upk2(acc[p][3], v3[0], v3[1]);
#pragma unroll
            for (int hh = 0; hh < 2; hh++) {
                const int r = 2 * p + hh;
                int4 m = *(const int4*)(mask + (size_t)(r0 + r) * 4096 + jb);
                float s = 0.f, t = 0.f, l;
                l = v0[hh] + bv.x; if (m.x) { float e = expf(l); s += e; t += e * l; } if (jb + 0 == aidx[r]) la_sm[r] = l;
                l = v1[hh] + bv.y; if (m.y) { float e = expf(l); s += e; t += e * l; } if (jb + 1 == aidx[r]) la_sm[r] = l;
                l = v2[hh] + bv.z; if (m.z) { float e = expf(l); s += e; t += e * l; } if (jb + 2 == aidx[r]) la_sm[r] = l;
                l = v3[hh] + bv.w; if (m.w) { float e = expf(l); s += e; t += e * l; } if (jb + 3 == aidx[r]) la_sm[r] = l;
#pragma unroll
                for (int o = 16; o > 0; o >>= 1) {
                    s += __shfl_down_sync(0xffffffffu, s, o);
                    t += __shfl_down_sync(0xffffffffu, t, o);
                }
                if (lane == 0) { redS[r][warp] = s; redT[r][warp] = t; }
            }
        }
        __syncthreads();
        if (tid < 16) {
            double s = 0.0, t = 0.0;
#pragma unroll
            for (int w = 0; w < 8; w++) { s += (double)redS[tid][w]; t += (double)redT[tid][w]; }
            sRun[tid] += s; tRun[tid] += t;
        }
        __syncthreads();
    }
    if (tid < 16) {
        const int i = r0 + tid;
        double S = sRun[tid], T1 = tRun[tid];
        double lS = log(S);
        g_ent_pim[i] = T1 / S - lS;
        g_lg_pim[i]  = (float)((double)la_sm[tid] - lS);
    }
}

// ------------------------------ vf broadcast (register-tiled) ----------------
__global__ __launch_bounds__(256) void vf_kernel(const float* __restrict__ ovp,
                                                 const float* __restrict__ ret)
{
    __shared__ float vp_s[8];
    __shared__ float part[8][257];
    const int tid = threadIdx.x, warp = tid >> 5, lane = tid & 31;
    const int r0 = blockIdx.x * 8;
    if (tid < 8) vp_s[tid] = g_vpred[r0 + tid];
    __syncthreads();

    float accr[8];
#pragma unroll
    for (int r = 0; r < 8; r++) accr[r] = 0.f;

#pragma unroll 1
    for (int c = 0; c < 4; c++) {
        const int j0 = c * 1024 + tid * 4;
        float4 rt4 = __ldg((const float4*)(ret + j0));
        float4 ov4 = __ldg((const float4*)(ovp + j0));
#pragma unroll
        for (int r = 0; r < 8; r++) {
            float vp = vp_s[r];
            float d, dc, t0, t1, t2, t3;
            d = vp - rt4.x; dc = ov4.x + fminf(fmaxf(vp - ov4.x, -CLIPF), CLIPF) - rt4.x; t0 = fmaxf(d*d, dc*dc);
            d = vp - rt4.y; dc = ov4.y + fminf(fmaxf(vp - ov4.y, -CLIPF), CLIPF) - rt4.y; t1 = fmaxf(d*d, dc*dc);
            d = vp - rt4.z; dc = ov4.z + fminf(fmaxf(vp - ov4.z, -CLIPF), CLIPF) - rt4.z; t2 = fmaxf(d*d, dc*dc);
            d = vp - rt4.w; dc = ov4.w + fminf(fmaxf(vp - ov4.w, -CLIPF), CLIPF) - rt4.w; t3 = fmaxf(d*d, dc*dc);
            accr[r] += (t0 + t1) + (t2 + t3);
        }
    }
#pragma unroll
    for (int r = 0; r < 8; r++) part[r][tid] = accr[r];
    __syncthreads();

    // warp w reduces row w (fixed order -> deterministic)
    double s = 0.0;
#pragma unroll
    for (int m = 0; m < 8; m++) s += (double)part[warp][m * 32 + lane];
#pragma unroll
    for (int o = 16; o > 0; o >>= 1) s += __shfl_down_sync(0xffffffffu, s, o);
    if (lane == 0) g_vf_row[r0 + warp] = s;
}

// ------------------------------ finalize ------------------------------------
__global__ __launch_bounds__(1024) void finalize_kernel(
    const float* __restrict__ GAE, const float* __restrict__ lgold, float* __restrict__ out)
{
    __shared__ double rA[1024], rB[1024];
    const int tid = threadIdx.x;
    double s1 = 0.0, s2 = 0.0;
    for (int i = tid; i < BT; i += 1024) { double g = GAE[i]; s1 += g; s2 += g * g; }
    rA[tid] = s1; rB[tid] = s2; __syncthreads();
    for (int o = 512; o > 0; o >>= 1) {
        if (tid < o) { rA[tid] += rA[tid + o]; rB[tid] += rB[tid + o]; }
        __syncthreads();
    }
    double mean = rA[0] / (double)BT;
    double var  = rB[0] / (double)BT - mean * mean;
    if (var < 0.0) var = 0.0;
    double denom = sqrt(var) + 1e-8;
    __syncthreads();

    double pg = 0.0, ent = 0.0, vf = 0.0;
    for (int i = tid; i < BT; i += 1024) {
        double g = ((double)GAE[i] - mean) / denom;
        float lgnew = ((i & 1) == 0) ? g_lg_pir[i] : g_lg_pim[i];
        double rt = exp((double)lgnew - (double)lgold[i]);
        double rtc = rt < (1.0 - CLIPF) ? (1.0 - CLIPF) : (rt > (1.0 + CLIPF) ? (1.0 + CLIPF) : rt);
        double p1 = -g * rt, p2 = -g * rtc;
        pg  += (p1 > p2) ? p1 : p2;
        ent += g_ent_pir[i] + g_ent_pim[i];
        vf  += g_vf_row[i];
    }
    rA[tid] = pg; rB[tid] = ent; __syncthreads();
    for (int o = 512; o > 0; o >>= 1) {
        if (tid < o) { rA[tid] += rA[tid + o]; rB[tid] += rB[tid + o]; }
        __syncthreads();
    }
    double pg_tot = rA[0], ent_tot = rB[0];
    __syncthreads();
    rA[tid] = vf; __syncthreads();
    for (int o = 512; o > 0; o >>= 1) {
        if (tid < o) rA[tid] += rA[tid + o];
        __syncthreads();
    }
    if (tid == 0) {
        double pg_loss = pg_tot / (double)BT;
        double entropy = -ent_tot;
        double vf_loss = 0.5 * rA[0] / ((double)BT * (double)BT);
        out[0] = (float)(pg_loss - entropy + vf_loss);
        out[1] = (float)pg_loss;
        out[2] = (float)entropy;
        out[3] = (float)vf_loss;
    }
}

// ------------------------------ launch --------------------------------------
extern "C" void kernel_launch(void* const* d_in, const int* in_sizes, int n_in,
                              void* d_out, int out_size) {
    const float* x      = (const float*)d_in[0];
    const int*   mask   = (const int*)  d_in[1];
    const float* lgold  = (const float*)d_in[2];
    const int*   ataken = (const int*)  d_in[3];
    const float* GAE    = (const float*)d_in[4];
    const float* ovp    = (const float*)d_in[5];
    const float* ret    = (const float*)d_in[6];
    const float* W1 = (const float*)d_in[7],  *b1 = (const float*)d_in[8];
    const float* W2 = (const float*)d_in[9],  *b2 = (const float*)d_in[10];
    const float* W3 = (const float*)d_in[11], *b3 = (const float*)d_in[12];
    const float* W4 = (const float*)d_in[13], *b4 = (const float*)d_in[14];
    const float* lk = (const float*)d_in[15];
    const float* lr = (const float*)d_in[16];
    const float* lb = (const float*)d_in[17];
    const float* pirW = (const float*)d_in[18], *pirb = (const float*)d_in[19];
    const float* pimW = (const float*)d_in[20], *pimb = (const float*)d_in[21];
    const float* vW   = (const float*)d_in[22], *vb   = (const float*)d_in[23];
    float* out = (float*)d_out;

    conv_kernel<<<512, 256>>>(x, W1, b1, W2, b2, W3, b3, W4, b4);
    xz_kernel<<<256, 256>>>(lk, lb);
    lstm_kernel<<<128, 256>>>(lr);
    pir_v_kernel<<<512, 256>>>(pirW, pirb, vW, vb, ataken);
    pim_kernel<<<256, 256>>>(pimW, pimb, mask, ataken);
    vf_kernel<<<512, 256>>>(ovp, ret);
    finalize_kernel<<<1, 1024>>>(GAE, lgold, out);
}

// round 9
// speedup vs baseline: 1.2028x; 1.2028x over previous
#include <cuda_runtime.h>
#include <math.h>

#define BT 4096
#define CLIPF 0.2f

// ------------------------------ scratch ------------------------------------
__device__ float  g_feat[BT * 256];
__device__ float  g_xz[BT * 1024];
__device__ float  g_hbuf[2 * 64 * 256];
__device__ float  g_lstm[BT * 256];
__device__ float  g_lg_pir[BT];
__device__ float  g_lg_pim[BT];
__device__ float  g_vpred[BT];
__device__ double g_ent_pir[BT];
__device__ double g_ent_pim[BT];
__device__ double g_vf_row[BT];

__device__ unsigned int          g_bar_cnt = 0u;
__device__ volatile unsigned int g_bar_gen = 0u;

__device__ __forceinline__ void grid_barrier(unsigned int nblocks) {
    __threadfence();
    __syncthreads();
    if (threadIdx.x == 0) {
        unsigned int gen = g_bar_gen;
        if (atomicAdd(&g_bar_cnt, 1u) == nblocks - 1u) {
            g_bar_cnt = 0u;
            __threadfence();
            g_bar_gen = gen + 1u;
        } else {
            while (g_bar_gen == gen) { __nanosleep(40); }
        }
    }
    __syncthreads();
    __threadfence();
}

__device__ __forceinline__ float leaky(float v) { return v > 0.f ? v : 0.2f * v; }
__device__ __forceinline__ float sigm(float v)  { return 1.f / (1.f + expf(-v)); }

// ------------------------------ conv stack ---------------------------------
__global__ __launch_bounds__(256) void conv_kernel(
    const float* __restrict__ x,
    const float* __restrict__ W1, const float* __restrict__ b1,
    const float* __restrict__ W2, const float* __restrict__ b2,
    const float* __restrict__ W3, const float* __restrict__ b3,
    const float* __restrict__ W4, const float* __restrict__ b4)
{
    __shared__ float w1[512], w2[2048];
    __shared__ float sb1[16], sb2[32], sb3[64], sb4[128];
    __shared__ float sin_[832], a1[384], a2[480], a3[128];
    const int tid = threadIdx.x;
    for (int i = tid; i < 512;  i += 256) w1[i] = W1[i];
    for (int i = tid; i < 2048; i += 256) w2[i] = W2[i];
    if (tid < 16)  sb1[tid] = b1[tid];
    if (tid < 32)  sb2[tid] = b2[tid];
    if (tid < 64)  sb3[tid] = b3[tid];
    if (tid < 128) sb4[tid] = b4[tid];

    for (int s = 0; s < 8; s++) {
        const int bt = blockIdx.x * 8 + s;
        __syncthreads();
        for (int i = tid; i < 832; i += 256) sin_[i] = x[(size_t)bt * 832 + i];
        __syncthreads();
        // conv1: (13,8,8)->(6,4,16) k2 s2
        for (int o = tid; o < 384; o += 256) {
            int oh = o >> 6, rem = o & 63, ow = rem >> 4, co = rem & 15;
            float acc = sb1[co];
#pragma unroll
            for (int kh = 0; kh < 2; kh++)
#pragma unroll
                for (int kw = 0; kw < 2; kw++)
#pragma unroll
                    for (int ci = 0; ci < 8; ci++)
                        acc = fmaf(sin_[(oh*2+kh)*64 + (ow*2+kw)*8 + ci],
                                   w1[((kh*2+kw)*8 + ci)*16 + co], acc);
            a1[o] = leaky(acc);
        }
        __syncthreads();
        // conv2: (6,4,16)->(5,3,32) k2 s1
        for (int o = tid; o < 480; o += 256) {
            int oh = o / 96, r2 = o % 96, ow = r2 >> 5, co = r2 & 31;
            float acc = sb2[co];
#pragma unroll
            for (int kh = 0; kh < 2; kh++)
#pragma unroll
                for (int kw = 0; kw < 2; kw++)
#pragma unroll
                    for (int ci = 0; ci < 16; ci++)
                        acc = fmaf(a1[(oh+kh)*64 + (ow+kw)*16 + ci],
                                   w2[((kh*2+kw)*16 + ci)*32 + co], acc);
            a2[o] = leaky(acc);
        }
        __syncthreads();
        // conv3: (5,3,32)->(2,1,64) k2 s2
        for (int o = tid; o < 128; o += 256) {
            int oh = o >> 6, co = o & 63;
            float acc = sb3[co];
#pragma unroll
            for (int kh = 0; kh < 2; kh++)
#pragma unroll
                for (int kw = 0; kw < 2; kw++)
#pragma unroll 8
                    for (int ci = 0; ci < 32; ci++)
                        acc = fmaf(a2[(oh*2+kh)*96 + kw*32 + ci],
                                   __ldg(&W3[((kh*2+kw)*32 + ci)*64 + co]), acc);
            a3[o] = leaky(acc);
        }
        __syncthreads();
        // conv4 1x1 -> (2,1,128); channels_first flatten: feat[c*2 + oh]
        {
            int o = tid, oh = o >> 7, co = o & 127;
            float acc = sb4[co];
#pragma unroll 8
            for (int ci = 0; ci < 64; ci++)
                acc = fmaf(a3[oh*64 + ci], __ldg(&W4[ci*128 + co]), acc);
            g_feat[(size_t)bt * 256 + co*2 + oh] = leaky(acc);
        }
    }
}

// ------------------------------ xz = feat @ Wk + b --------------------------
__global__ __launch_bounds__(128) void xz_kernel(const float* __restrict__ Wk,
                                                 const float* __restrict__ lb)
{
    __shared__ float a_sm[8][256];
    const int tid = threadIdx.x;
    const int r0 = blockIdx.y * 8;
    for (int i = tid; i < 8 * 256; i += 128)
        a_sm[i >> 8][i & 255] = g_feat[(size_t)(r0 + (i >> 8)) * 256 + (i & 255)];
    __syncthreads();

    const int j0 = blockIdx.x * 512 + tid * 4;
    float acc[8][4];
#pragma unroll
    for (int r = 0; r < 8; r++) { acc[r][0]=0.f; acc[r][1]=0.f; acc[r][2]=0.f; acc[r][3]=0.f; }

#pragma unroll 1
    for (int k = 0; k < 256; k += 4) {
        float4 w0 = __ldg((const float4*)(Wk + (size_t)(k+0)*1024 + j0));
        float4 w1 = __ldg((const float4*)(Wk + (size_t)(k+1)*1024 + j0));
        float4 w2 = __ldg((const float4*)(Wk + (size_t)(k+2)*1024 + j0));
        float4 w3 = __ldg((const float4*)(Wk + (size_t)(k+3)*1024 + j0));
#pragma unroll
        for (int r = 0; r < 8; r++) {
            float4 a = *(const float4*)&a_sm[r][k];
            acc[r][0] = fmaf(a.w,w3.x,fmaf(a.z,w2.x,fmaf(a.y,w1.x,fmaf(a.x,w0.x,acc[r][0]))));
            acc[r][1] = fmaf(a.w,w3.y,fmaf(a.z,w2.y,fmaf(a.y,w1.y,fmaf(a.x,w0.y,acc[r][1]))));
            acc[r][2] = fmaf(a.w,w3.z,fmaf(a.z,w2.z,fmaf(a.y,w1.z,fmaf(a.x,w0.z,acc[r][2]))));
            acc[r][3] = fmaf(a.w,w3.w,fmaf(a.z,w2.w,fmaf(a.y,w1.w,fmaf(a.x,w0.w,acc[r][3]))));
        }
    }
    float4 bv = *(const float4*)(lb + j0);
#pragma unroll
    for (int r = 0; r < 8; r++) {
        float4 o; o.x=acc[r][0]+bv.x; o.y=acc[r][1]+bv.y; o.z=acc[r][2]+bv.z; o.w=acc[r][3]+bv.w;
        *(float4*)&g_xz[(size_t)(r0 + r) * 1024 + j0] = o;
    }
}

// ------------------------------ LSTM (persistent, 128 blocks) ---------------
__global__ __launch_bounds__(256) void lstm_kernel(const float* __restrict__ Wr)
{
    __shared__ float w_sm[8][256];   // [gate*2+unit][k]
    __shared__ float z_sm[64][4][2];
    __shared__ float c_sm[64][2];
    const int tid = threadIdx.x;
    const int j0 = blockIdx.x * 2;

    for (int i = tid; i < 2048; i += 256) {
        int col = i >> 8, k = i & 255, gg = col >> 1, u = col & 1;
        w_sm[col][k] = Wr[(size_t)k * 1024 + gg * 256 + j0 + u];
    }
    if (tid < 128) c_sm[tid >> 1][tid & 1] = 0.f;
    __syncthreads();

    const int b = tid >> 2;
    const int g = tid & 3;

    for (int t = 0; t < 64; t++) {
        const size_t row = (size_t)(b * 64 + t);
        float acc0 = g_xz[row * 1024 + g * 256 + j0];
        float acc1 = g_xz[row * 1024 + g * 256 + j0 + 1];
        if (t > 0) {
            const float* h = g_hbuf + ((t - 1) & 1) * (64 * 256) + b * 256;
            const float* wa = w_sm[g * 2 + 0];
            const float* wb = w_sm[g * 2 + 1];
#pragma unroll 4
            for (int k = 0; k < 256; k += 4) {
                float4 h4 = __ldcg((const float4*)(h + k));
                float4 wA = *(const float4*)(wa + k);
                float4 wB = *(const float4*)(wb + k);
                acc0 = fmaf(h4.w,wA.w,fmaf(h4.z,wA.z,fmaf(h4.y,wA.y,fmaf(h4.x,wA.x,acc0))));
                acc1 = fmaf(h4.w,wB.w,fmaf(h4.z,wB.z,fmaf(h4.y,wB.y,fmaf(h4.x,wB.x,acc1))));
            }
        }
        z_sm[b][g][0] = acc0;
        z_sm[b][g][1] = acc1;
        __syncthreads();
        if (tid < 128) {
            int b2 = tid >> 1, u = tid & 1;
            float zi = z_sm[b2][0][u], zf = z_sm[b2][1][u];
            float zg = z_sm[b2][2][u], zo = z_sm[b2][3][u];
            float c = sigm(zf) * c_sm[b2][u] + sigm(zi) * tanhf(zg);
            float hv = sigm(zo) * tanhf(c);
            c_sm[b2][u] = c;
            __stcg(&g_hbuf[(t & 1) * (64 * 256) + b2 * 256 + j0 + u], hv);
            g_lstm[(size_t)(b2 * 64 + t) * 256 + j0 + u] = hv;
        }
        grid_barrier(gridDim.x);
    }
}

// ------------------------------ pir head + vpred (smem-staged) ---------------
__global__ __launch_bounds__(256) void pir_v_kernel(
    const float* __restrict__ pirW, const float* __restrict__ pirb,
    const float* __restrict__ vW,  const float* __restrict__ vb,
    const int* __restrict__ a_taken)
{
    __shared__ float ws[256 * 36];
    __shared__ float vws[256];
    __shared__ float hs[8][256];
    const int tid = threadIdx.x, warp = tid >> 5, lane = tid & 31;
    const int r0 = blockIdx.x * 8;

    for (int i = tid; i < 9216; i += 256) ws[i] = pirW[i];
    vws[tid] = vW[tid];
    for (int i = tid; i < 2048; i += 256)
        hs[i >> 8][i & 255] = g_lstm[(size_t)(r0 + (i >> 8)) * 256 + (i & 255)];
    __syncthreads();

    const int i = r0 + warp;
    float acc0 = 0.f, acc1 = 0.f, accv = 0.f;
#pragma unroll 4
    for (int k = 0; k < 256; k++) {
        float hk = hs[warp][k];
        acc0 = fmaf(hk, ws[k * 36 + lane], acc0);
        if (lane < 4) acc1 = fmaf(hk, ws[k * 36 + 32 + lane], acc1);
    }
    for (int k = lane; k < 256; k += 32) accv = fmaf(hs[warp][k], vws[k], accv);

    float l0 = acc0 + __ldg(&pirb[lane]);
    float l1 = (lane < 4) ? acc1 + __ldg(&pirb[lane + 32]) : 0.f;
    float e0 = expf(l0);
    float e1 = (lane < 4) ? expf(l1) : 0.f;
    float cs = e0 + e1;
    float ct = e0 * l0 + ((lane < 4) ? e1 * l1 : 0.f);
#pragma unroll
    for (int o = 16; o > 0; o >>= 1) {
        cs   += __shfl_down_sync(0xffffffffu, cs, o);
        ct   += __shfl_down_sync(0xffffffffu, ct, o);
        accv += __shfl_down_sync(0xffffffffu, accv, o);
    }
    float S = __shfl_sync(0xffffffffu, cs, 0);
    int a = a_taken[i];
    float laA = __shfl_sync(0xffffffffu, l0, a & 31);
    float laB = __shfl_sync(0xffffffffu, l1, a & 31);
    float la = (a < 32) ? laA : laB;
    if (lane == 0) {
        double lS = log((double)S);
        g_ent_pir[i] = (double)ct / (double)S - lS;   // sum p*log p
        g_lg_pir[i]  = (float)((double)la - lS);
        g_vpred[i]   = accv + vb[0];
    }
}

// ------------------------------ pim GEMM + fused epilogue --------------------
__global__ __launch_bounds__(256) void pim_kernel(
    const float* __restrict__ pimW, const float* __restrict__ pimb,
    const int* __restrict__ mask, const int* __restrict__ a_taken)
{
    __shared__ float a_sm[16][256];
    __shared__ float redS[16][8], redT[16][8];
    __shared__ double sRun[16], tRun[16];
    __shared__ float la_sm[16];
    __shared__ int aidx[16];
    const int tid = threadIdx.x, lane = tid & 31, warp = tid >> 5;
    const int r0 = blockIdx.x * 16;

    for (int i = tid; i < 16 * 256; i += 256)
        a_sm[i >> 8][i & 255] = g_lstm[(size_t)(r0 + (i >> 8)) * 256 + (i & 255)];
    if (tid < 16) { sRun[tid] = 0.0; tRun[tid] = 0.0; aidx[tid] = a_taken[r0 + tid]; la_sm[tid] = 0.f; }
    __syncthreads();

#pragma unroll 1
    for (int tile = 0; tile < 4; tile++) {
        const int jb = tile * 1024 + tid * 4;
        const float* Wp = pimW + jb;
        float acc[16][4];
#pragma unroll
        for (int r = 0; r < 16; r++) { acc[r][0]=0.f; acc[r][1]=0.f; acc[r][2]=0.f; acc[r][3]=0.f; }
#pragma unroll 1
        for (int k = 0; k < 256; k += 4) {
            float4 w0 = __ldg((const float4*)(Wp + (size_t)(k+0)*4096));
            float4 w1 = __ldg((const float4*)(Wp + (size_t)(k+1)*4096));
            float4 w2 = __ldg((const float4*)(Wp + (size_t)(k+2)*4096));
            float4 w3 = __ldg((const float4*)(Wp + (size_t)(k+3)*4096));
#pragma unroll
            for (int r = 0; r < 16; r++) {
                float4 a = *(const float4*)&a_sm[r][k];
                acc[r][0] = fmaf(a.w,w3.x,fmaf(a.z,w2.x,fmaf(a.y,w1.x,fmaf(a.x,w0.x,acc[r][0]))));
                acc[r][1] = fmaf(a.w,w3.y,fmaf(a.z,w2.y,fmaf(a.y,w1.y,fmaf(a.x,w0.y,acc[r][1]))));
                acc[r][2] = fmaf(a.w,w3.z,fmaf(a.z,w2.z,fmaf(a.y,w1.z,fmaf(a.x,w0.z,acc[r][2]))));
                acc[r][3] = fmaf(a.w,w3.w,fmaf(a.z,w2.w,fmaf(a.y,w1.w,fmaf(a.x,w0.w,acc[r][3]))));
            }
        }
        float4 bv = __ldg((const float4*)(pimb + jb));
#pragma unroll 1
        for (int r = 0; r < 16; r++) {
            int4 m = *(const int4*)(mask + (size_t)(r0 + r) * 4096 + jb);
            float s = 0.f, t = 0.f, l;
            l = acc[r][0] + bv.x; if (m.x) { float e = expf(l); s += e; t += e * l; } if (jb + 0 == aidx[r]) la_sm[r] = l;
            l = acc[r][1] + bv.y; if (m.y) { float e = expf(l); s += e; t += e * l; } if (jb + 1 == aidx[r]) la_sm[r] = l;
            l = acc[r][2] + bv.z; if (m.z) { float e = expf(l); s += e; t += e * l; } if (jb + 2 == aidx[r]) la_sm[r] = l;
            l = acc[r][3] + bv.w; if (m.w) { float e = expf(l); s += e; t += e * l; } if (jb + 3 == aidx[r]) la_sm[r] = l;
#pragma unroll
            for (int o = 16; o > 0; o >>= 1) {
                s += __shfl_down_sync(0xffffffffu, s, o);
                t += __shfl_down_sync(0xffffffffu, t, o);
            }
            if (lane == 0) { redS[r][warp] = s; redT[r][warp] = t; }
        }
        __syncthreads();
        if (tid < 16) {
            double s = 0.0, t = 0.0;
#pragma unroll
            for (int w = 0; w < 8; w++) { s += (double)redS[tid][w]; t += (double)redT[tid][w]; }
            sRun[tid] += s; tRun[tid] += t;
        }
        __syncthreads();
    }
    if (tid < 16) {
        const int i = r0 + tid;
        double S = sRun[tid], T1 = tRun[tid];
        double lS = log(S);
        g_ent_pim[i] = T1 / S - lS;                      // sum_masked p*log p
        g_lg_pim[i]  = (float)((double)la_sm[tid] - lS); // log pim[i, a]
    }
}

// ------------------------------ vf broadcast (register-tiled) ----------------
__global__ __launch_bounds__(256) void vf_kernel(const float* __restrict__ ovp,
                                                 const float* __restrict__ ret)
{
    __shared__ float vp_s[8];
    __shared__ float part[8][257];
    const int tid = threadIdx.x, warp = tid >> 5, lane = tid & 31;
    const int r0 = blockIdx.x * 8;
    if (tid < 8) vp_s[tid] = g_vpred[r0 + tid];
    __syncthreads();

    float accr[8];
#pragma unroll
    for (int r = 0; r < 8; r++) accr[r] = 0.f;

#pragma unroll 1
    for (int c = 0; c < 4; c++) {
        const int j0 = c * 1024 + tid * 4;
        float4 rt4 = __ldg((const float4*)(ret + j0));
        float4 ov4 = __ldg((const float4*)(ovp + j0));
#pragma unroll
        for (int r = 0; r < 8; r++) {
            float vp = vp_s[r];
            float d, dc, t0, t1, t2, t3;
            d = vp - rt4.x; dc = ov4.x + fminf(fmaxf(vp - ov4.x, -CLIPF), CLIPF) - rt4.x; t0 = fmaxf(d*d, dc*dc);
            d = vp - rt4.y; dc = ov4.y + fminf(fmaxf(vp - ov4.y, -CLIPF), CLIPF) - rt4.y; t1 = fmaxf(d*d, dc*dc);
            d = vp - rt4.z; dc = ov4.z + fminf(fmaxf(vp - ov4.z, -CLIPF), CLIPF) - rt4.z; t2 = fmaxf(d*d, dc*dc);
            d = vp - rt4.w; dc = ov4.w + fminf(fmaxf(vp - ov4.w, -CLIPF), CLIPF) - rt4.w; t3 = fmaxf(d*d, dc*dc);
            accr[r] += (t0 + t1) + (t2 + t3);
        }
    }
#pragma unroll
    for (int r = 0; r < 8; r++) part[r][tid] = accr[r];
    __syncthreads();

    // warp w reduces row w (fixed order -> deterministic)
    double s = 0.0;
#pragma unroll
    for (int m = 0; m < 8; m++) s += (double)part[warp][m * 32 + lane];
#pragma unroll
    for (int o = 16; o > 0; o >>= 1) s += __shfl_down_sync(0xffffffffu, s, o);
    if (lane == 0) g_vf_row[r0 + warp] = s;
}

// ------------------------------ finalize ------------------------------------
__global__ __launch_bounds__(1024) void finalize_kernel(
    const float* __restrict__ GAE, const float* __restrict__ lgold, float* __restrict__ out)
{
    __shared__ double rA[1024], rB[1024];
    const int tid = threadIdx.x;
    double s1 = 0.0, s2 = 0.0;
    for (int i = tid; i < BT; i += 1024) { double g = GAE[i]; s1 += g; s2 += g * g; }
    rA[tid] = s1; rB[tid] = s2; __syncthreads();
    for (int o = 512; o > 0; o >>= 1) {
        if (tid < o) { rA[tid] += rA[tid + o]; rB[tid] += rB[tid + o]; }
        __syncthreads();
    }
    double mean = rA[0] / (double)BT;
    double var  = rB[0] / (double)BT - mean * mean;
    if (var < 0.0) var = 0.0;
    double denom = sqrt(var) + 1e-8;
    __syncthreads();

    double pg = 0.0, ent = 0.0, vf = 0.0;
    for (int i = tid; i < BT; i += 1024) {
        double g = ((double)GAE[i] - mean) / denom;
        float lgnew = ((i & 1) == 0) ? g_lg_pir[i] : g_lg_pim[i];
        double rt = exp((double)lgnew - (double)lgold[i]);
        double rtc = rt < (1.0 - CLIPF) ? (1.0 - CLIPF) : (rt > (1.0 + CLIPF) ? (1.0 + CLIPF) : rt);
        double p1 = -g * rt, p2 = -g * rtc;
        pg  += (p1 > p2) ? p1 : p2;
        ent += g_ent_pir[i] + g_ent_pim[i];
        vf  += g_vf_row[i];
    }
    rA[tid] = pg; rB[tid] = ent; __syncthreads();
    for (int o = 512; o > 0; o >>= 1) {
        if (tid < o) { rA[tid] += rA[tid + o]; rB[tid] += rB[tid + o]; }
        __syncthreads();
    }
    double pg_tot = rA[0], ent_tot = rB[0];
    __syncthreads();
    rA[tid] = vf; __syncthreads();
    for (int o = 512; o > 0; o >>= 1) {
        if (tid < o) rA[tid] += rA[tid + o];
        __syncthreads();
    }
    if (tid == 0) {
        double pg_loss = pg_tot / (double)BT;
        double entropy = -ent_tot;
        double vf_loss = 0.5 * rA[0] / ((double)BT * (double)BT);
        out[0] = (float)(pg_loss - entropy + vf_loss);
        out[1] = (float)pg_loss;
        out[2] = (float)entropy;
        out[3] = (float)vf_loss;
    }
}

// ------------------------------ launch --------------------------------------
extern "C" void kernel_launch(void* const* d_in, const int* in_sizes, int n_in,
                              void* d_out, int out_size) {
    const float* x      = (const float*)d_in[0];
    const int*   mask   = (const int*)  d_in[1];
    const float* lgold  = (const float*)d_in[2];
    const int*   ataken = (const int*)  d_in[3];
    const float* GAE    = (const float*)d_in[4];
    const float* ovp    = (const float*)d_in[5];
    const float* ret    = (const float*)d_in[6];
    const float* W1 = (const float*)d_in[7],  *b1 = (const float*)d_in[8];
    const float* W2 = (const float*)d_in[9],  *b2 = (const float*)d_in[10];
    const float* W3 = (const float*)d_in[11], *b3 = (const float*)d_in[12];
    const float* W4 = (const float*)d_in[13], *b4 = (const float*)d_in[14];
    const float* lk = (const float*)d_in[15];
    const float* lr = (const float*)d_in[16];
    const float* lb = (const float*)d_in[17];
    const float* pirW = (const float*)d_in[18], *pirb = (const float*)d_in[19];
    const float* pimW = (const float*)d_in[20], *pimb = (const float*)d_in[21];
    const float* vW   = (const float*)d_in[22], *vb   = (const float*)d_in[23];
    float* out = (float*)d_out;

    conv_kernel<<<512, 256>>>(x, W1, b1, W2, b2, W3, b3, W4, b4);
    xz_kernel<<<dim3(2, 512), 128>>>(lk, lb);
    lstm_kernel<<<128, 256>>>(lr);
    pir_v_kernel<<<512, 256>>>(pirW, pirb, vW, vb, ataken);
    pim_kernel<<<256, 256>>>(pimW, pimb, mask, ataken);
    vf_kernel<<<512, 256>>>(ovp, ret);
    finalize_kernel<<<1, 1024>>>(GAE, lgold, out);
}

// round 10
// speedup vs baseline: 1.2276x; 1.0206x over previous
#include <cuda_runtime.h>
#include <math.h>

#define BT 4096
#define CLIPF 0.2f

// ------------------------------ scratch ------------------------------------
__device__ float  g_feat[BT * 256];
__device__ float  g_xz[BT * 1024];
__device__ float  g_hbuf[2 * 64 * 256];
__device__ float  g_lstm[BT * 256];
__device__ float  g_lg_pir[BT];
__device__ float  g_lg_pim[BT];
__device__ float  g_vpred[BT];
__device__ double g_ent_pir[BT];
__device__ double g_ent_pim[BT];
__device__ double g_vf_row[BT];

__device__ unsigned int g_bar_cnt = 0u;
__device__ unsigned int g_bar_gen = 0u;

__device__ __forceinline__ unsigned int ld_acq_gpu(const unsigned int* p) {
    unsigned int v;
    asm volatile("ld.acquire.gpu.global.u32 %0, [%1];" : "=r"(v) : "l"(p) : "memory");
    return v;
}

// Release/acquire grid barrier: no membar.gl (no L1D flush), no nanosleep.
// Cumulativity: __syncthreads orders all threads' prior stores before thread
// 0's atom.release; observer's ld.acquire + __syncthreads extends visibility
// to all its threads (PTX memory-model causality).
__device__ __forceinline__ void grid_barrier(unsigned int nblocks) {
    __syncthreads();
    if (threadIdx.x == 0) {
        unsigned int gen = ld_acq_gpu(&g_bar_gen);
        unsigned int old;
        asm volatile("atom.release.gpu.global.add.u32 %0, [%1], %2;"
                     : "=r"(old) : "l"(&g_bar_cnt), "r"(1u) : "memory");
        if (old == nblocks - 1u) {
            g_bar_cnt = 0u;   // ordered before gen publication by st.release
            asm volatile("st.release.gpu.global.u32 [%0], %1;"
                         :: "l"(&g_bar_gen), "r"(gen + 1u) : "memory");
        } else {
            while (ld_acq_gpu(&g_bar_gen) == gen) { }
        }
    }
    __syncthreads();
}

__device__ __forceinline__ float leaky(float v) { return v > 0.f ? v : 0.2f * v; }
__device__ __forceinline__ float sigm(float v)  { return 1.f / (1.f + expf(-v)); }

// ------------------------------ conv stack ---------------------------------
__global__ __launch_bounds__(256) void conv_kernel(
    const float* __restrict__ x,
    const float* __restrict__ W1, const float* __restrict__ b1,
    const float* __restrict__ W2, const float* __restrict__ b2,
    const float* __restrict__ W3, const float* __restrict__ b3,
    const float* __restrict__ W4, const float* __restrict__ b4)
{
    __shared__ float w1[512], w2[2048];
    __shared__ float sb1[16], sb2[32], sb3[64], sb4[128];
    __shared__ float sin_[832], a1[384], a2[480], a3[128];
    const int tid = threadIdx.x;
    for (int i = tid; i < 512;  i += 256) w1[i] = W1[i];
    for (int i = tid; i < 2048; i += 256) w2[i] = W2[i];
    if (tid < 16)  sb1[tid] = b1[tid];
    if (tid < 32)  sb2[tid] = b2[tid];
    if (tid < 64)  sb3[tid] = b3[tid];
    if (tid < 128) sb4[tid] = b4[tid];

    for (int s = 0; s < 8; s++) {
        const int bt = blockIdx.x * 8 + s;
        __syncthreads();
        for (int i = tid; i < 832; i += 256) sin_[i] = x[(size_t)bt * 832 + i];
        __syncthreads();
        // conv1: (13,8,8)->(6,4,16) k2 s2
        for (int o = tid; o < 384; o += 256) {
            int oh = o >> 6, rem = o & 63, ow = rem >> 4, co = rem & 15;
            float acc = sb1[co];
#pragma unroll
            for (int kh = 0; kh < 2; kh++)
#pragma unroll
                for (int kw = 0; kw < 2; kw++)
#pragma unroll
                    for (int ci = 0; ci < 8; ci++)
                        acc = fmaf(sin_[(oh*2+kh)*64 + (ow*2+kw)*8 + ci],
                                   w1[((kh*2+kw)*8 + ci)*16 + co], acc);
            a1[o] = leaky(acc);
        }
        __syncthreads();
        // conv2: (6,4,16)->(5,3,32) k2 s1
        for (int o = tid; o < 480; o += 256) {
            int oh = o / 96, r2 = o % 96, ow = r2 >> 5, co = r2 & 31;
            float acc = sb2[co];
#pragma unroll
            for (int kh = 0; kh < 2; kh++)
#pragma unroll
                for (int kw = 0; kw < 2; kw++)
#pragma unroll
                    for (int ci = 0; ci < 16; ci++)
                        acc = fmaf(a1[(oh+kh)*64 + (ow+kw)*16 + ci],
                                   w2[((kh*2+kw)*16 + ci)*32 + co], acc);
            a2[o] = leaky(acc);
        }
        __syncthreads();
        // conv3: (5,3,32)->(2,1,64) k2 s2
        for (int o = tid; o < 128; o += 256) {
            int oh = o >> 6, co = o & 63;
            float acc = sb3[co];
#pragma unroll
            for (int kh = 0; kh < 2; kh++)
#pragma unroll
                for (int kw = 0; kw < 2; kw++)
#pragma unroll 8
                    for (int ci = 0; ci < 32; ci++)
                        acc = fmaf(a2[(oh*2+kh)*96 + kw*32 + ci],
                                   __ldg(&W3[((kh*2+kw)*32 + ci)*64 + co]), acc);
            a3[o] = leaky(acc);
        }
        __syncthreads();
        // conv4 1x1 -> (2,1,128); channels_first flatten: feat[c*2 + oh]
        {
            int o = tid, oh = o >> 7, co = o & 127;
            float acc = sb4[co];
#pragma unroll 8
            for (int ci = 0; ci < 64; ci++)
                acc = fmaf(a3[oh*64 + ci], __ldg(&W4[ci*128 + co]), acc);
            g_feat[(size_t)bt * 256 + co*2 + oh] = leaky(acc);
        }
    }
}

// ------------------------------ xz = feat @ Wk + b --------------------------
__global__ __launch_bounds__(128) void xz_kernel(const float* __restrict__ Wk,
                                                 const float* __restrict__ lb)
{
    __shared__ float a_sm[8][256];
    const int tid = threadIdx.x;
    const int r0 = blockIdx.y * 8;
    for (int i = tid; i < 8 * 256; i += 128)
        a_sm[i >> 8][i & 255] = g_feat[(size_t)(r0 + (i >> 8)) * 256 + (i & 255)];
    __syncthreads();

    const int j0 = blockIdx.x * 512 + tid * 4;
    float acc[8][4];
#pragma unroll
    for (int r = 0; r < 8; r++) { acc[r][0]=0.f; acc[r][1]=0.f; acc[r][2]=0.f; acc[r][3]=0.f; }

#pragma unroll 1
    for (int k = 0; k < 256; k += 4) {
        float4 w0 = __ldg((const float4*)(Wk + (size_t)(k+0)*1024 + j0));
        float4 w1 = __ldg((const float4*)(Wk + (size_t)(k+1)*1024 + j0));
        float4 w2 = __ldg((const float4*)(Wk + (size_t)(k+2)*1024 + j0));
        float4 w3 = __ldg((const float4*)(Wk + (size_t)(k+3)*1024 + j0));
#pragma unroll
        for (int r = 0; r < 8; r++) {
            float4 a = *(const float4*)&a_sm[r][k];
            acc[r][0] = fmaf(a.w,w3.x,fmaf(a.z,w2.x,fmaf(a.y,w1.x,fmaf(a.x,w0.x,acc[r][0]))));
            acc[r][1] = fmaf(a.w,w3.y,fmaf(a.z,w2.y,fmaf(a.y,w1.y,fmaf(a.x,w0.y,acc[r][1]))));
            acc[r][2] = fmaf(a.w,w3.z,fmaf(a.z,w2.z,fmaf(a.y,w1.z,fmaf(a.x,w0.z,acc[r][2]))));
            acc[r][3] = fmaf(a.w,w3.w,fmaf(a.z,w2.w,fmaf(a.y,w1.w,fmaf(a.x,w0.w,acc[r][3]))));
        }
    }
    float4 bv = *(const float4*)(lb + j0);
#pragma unroll
    for (int r = 0; r < 8; r++) {
        float4 o; o.x=acc[r][0]+bv.x; o.y=acc[r][1]+bv.y; o.z=acc[r][2]+bv.z; o.w=acc[r][3]+bv.w;
        *(float4*)&g_xz[(size_t)(r0 + r) * 1024 + j0] = o;
    }
}

// ------------------------------ LSTM (persistent, 128 blocks) ---------------
__global__ __launch_bounds__(256) void lstm_kernel(const float* __restrict__ Wr)
{
    __shared__ float w_sm[8][256];   // [gate*2+unit][k]
    __shared__ float z_sm[64][4][2];
    __shared__ float c_sm[64][2];
    const int tid = threadIdx.x;
    const int j0 = blockIdx.x * 2;

    for (int i = tid; i < 2048; i += 256) {
        int col = i >> 8, k = i & 255, gg = col >> 1, u = col & 1;
        w_sm[col][k] = Wr[(size_t)k * 1024 + gg * 256 + j0 + u];
    }
    if (tid < 128) c_sm[tid >> 1][tid & 1] = 0.f;
    __syncthreads();

    const int b = tid >> 2;
    const int g = tid & 3;

    for (int t = 0; t < 64; t++) {
        const size_t row = (size_t)(b * 64 + t);
        float acc0 = g_xz[row * 1024 + g * 256 + j0];
        float acc1 = g_xz[row * 1024 + g * 256 + j0 + 1];
        if (t > 0) {
            const float* h = g_hbuf + ((t - 1) & 1) * (64 * 256) + b * 256;
            const float* wa = w_sm[g * 2 + 0];
            const float* wb = w_sm[g * 2 + 1];
#pragma unroll 4
            for (int k = 0; k < 256; k += 4) {
                float4 h4 = __ldcg((const float4*)(h + k));
                float4 wA = *(const float4*)(wa + k);
                float4 wB = *(const float4*)(wb + k);
                acc0 = fmaf(h4.w,wA.w,fmaf(h4.z,wA.z,fmaf(h4.y,wA.y,fmaf(h4.x,wA.x,acc0))));
                acc1 = fmaf(h4.w,wB.w,fmaf(h4.z,wB.z,fmaf(h4.y,wB.y,fmaf(h4.x,wB.x,acc1))));
            }
        }
        z_sm[b][g][0] = acc0;
        z_sm[b][g][1] = acc1;
        __syncthreads();
        if (tid < 128) {
            int b2 = tid >> 1, u = tid & 1;
            float zi = z_sm[b2][0][u], zf = z_sm[b2][1][u];
            float zg = z_sm[b2][2][u], zo = z_sm[b2][3][u];
            float c = sigm(zf) * c_sm[b2][u] + sigm(zi) * tanhf(zg);
            float hv = sigm(zo) * tanhf(c);
            c_sm[b2][u] = c;
            __stcg(&g_hbuf[(t & 1) * (64 * 256) + b2 * 256 + j0 + u], hv);
            g_lstm[(size_t)(b2 * 64 + t) * 256 + j0 + u] = hv;
        }
        grid_barrier(gridDim.x);
    }
}

// ------------------------------ pir head + vpred (smem-staged) ---------------
__global__ __launch_bounds__(256) void pir_v_kernel(
    const float* __restrict__ pirW, const float* __restrict__ pirb,
    const float* __restrict__ vW,  const float* __restrict__ vb,
    const int* __restrict__ a_taken)
{
    __shared__ float ws[256 * 36];
    __shared__ float vws[256];
    __shared__ float hs[8][256];
    const int tid = threadIdx.x, warp = tid >> 5, lane = tid & 31;
    const int r0 = blockIdx.x * 8;

    for (int i = tid; i < 9216; i += 256) ws[i] = pirW[i];
    vws[tid] = vW[tid];
    for (int i = tid; i < 2048; i += 256)
        hs[i >> 8][i & 255] = g_lstm[(size_t)(r0 + (i >> 8)) * 256 + (i & 255)];
    __syncthreads();

    const int i = r0 + warp;
    float acc0 = 0.f, acc1 = 0.f, accv = 0.f;
#pragma unroll 4
    for (int k = 0; k < 256; k++) {
        float hk = hs[warp][k];
        acc0 = fmaf(hk, ws[k * 36 + lane], acc0);
        if (lane < 4) acc1 = fmaf(hk, ws[k * 36 + 32 + lane], acc1);
    }
    for (int k = lane; k < 256; k += 32) accv = fmaf(hs[warp][k], vws[k], accv);

    float l0 = acc0 + __ldg(&pirb[lane]);
    float l1 = (lane < 4) ? acc1 + __ldg(&pirb[lane + 32]) : 0.f;
    float e0 = expf(l0);
    float e1 = (lane < 4) ? expf(l1) : 0.f;
    float cs = e0 + e1;
    float ct = e0 * l0 + ((lane < 4) ? e1 * l1 : 0.f);
#pragma unroll
    for (int o = 16; o > 0; o >>= 1) {
        cs   += __shfl_down_sync(0xffffffffu, cs, o);
        ct   += __shfl_down_sync(0xffffffffu, ct, o);
        accv += __shfl_down_sync(0xffffffffu, accv, o);
    }
    float S = __shfl_sync(0xffffffffu, cs, 0);
    int a = a_taken[i];
    float laA = __shfl_sync(0xffffffffu, l0, a & 31);
    float laB = __shfl_sync(0xffffffffu, l1, a & 31);
    float la = (a < 32) ? laA : laB;
    if (lane == 0) {
        double lS = log((double)S);
        g_ent_pir[i] = (double)ct / (double)S - lS;   // sum p*log p
        g_lg_pir[i]  = (float)((double)la - lS);
        g_vpred[i]   = accv + vb[0];
    }
}

// ------------------------------ pim GEMM + fused epilogue --------------------
__global__ __launch_bounds__(256) void pim_kernel(
    const float* __restrict__ pimW, const float* __restrict__ pimb,
    const int* __restrict__ mask, const int* __restrict__ a_taken)
{
    __shared__ float a_sm[16][256];
    __shared__ float redS[16][8], redT[16][8];
    __shared__ double sRun[16], tRun[16];
    __shared__ float la_sm[16];
    __shared__ int aidx[16];
    const int tid = threadIdx.x, lane = tid & 31, warp = tid >> 5;
    const int r0 = blockIdx.x * 16;

    for (int i = tid; i < 16 * 256; i += 256)
        a_sm[i >> 8][i & 255] = g_lstm[(size_t)(r0 + (i >> 8)) * 256 + (i & 255)];
    if (tid < 16) { sRun[tid] = 0.0; tRun[tid] = 0.0; aidx[tid] = a_taken[r0 + tid]; la_sm[tid] = 0.f; }
    __syncthreads();

#pragma unroll 1
    for (int tile = 0; tile < 4; tile++) {
        const int jb = tile * 1024 + tid * 4;
        const float* Wp = pimW + jb;
        float acc[16][4];
#pragma unroll
        for (int r = 0; r < 16; r++) { acc[r][0]=0.f; acc[r][1]=0.f; acc[r][2]=0.f; acc[r][3]=0.f; }
#pragma unroll 1
        for (int k = 0; k < 256; k += 4) {
            float4 w0 = __ldg((const float4*)(Wp + (size_t)(k+0)*4096));
            float4 w1 = __ldg((const float4*)(Wp + (size_t)(k+1)*4096));
            float4 w2 = __ldg((const float4*)(Wp + (size_t)(k+2)*4096));
            float4 w3 = __ldg((const float4*)(Wp + (size_t)(k+3)*4096));
#pragma unroll
            for (int r = 0; r < 16; r++) {
                float4 a = *(const float4*)&a_sm[r][k];
                acc[r][0] = fmaf(a.w,w3.x,fmaf(a.z,w2.x,fmaf(a.y,w1.x,fmaf(a.x,w0.x,acc[r][0]))));
                acc[r][1] = fmaf(a.w,w3.y,fmaf(a.z,w2.y,fmaf(a.y,w1.y,fmaf(a.x,w0.y,acc[r][1]))));
                acc[r][2] = fmaf(a.w,w3.z,fmaf(a.z,w2.z,fmaf(a.y,w1.z,fmaf(a.x,w0.z,acc[r][2]))));
                acc[r][3] = fmaf(a.w,w3.w,fmaf(a.z,w2.w,fmaf(a.y,w1.w,fmaf(a.x,w0.w,acc[r][3]))));
            }
        }
        float4 bv = __ldg((const float4*)(pimb + jb));
#pragma unroll 1
        for (int r = 0; r < 16; r++) {
            int4 m = *(const int4*)(mask + (size_t)(r0 + r) * 4096 + jb);
            float s = 0.f, t = 0.f, l;
            l = acc[r][0] + bv.x; if (m.x) { float e = expf(l); s += e; t += e * l; } if (jb + 0 == aidx[r]) la_sm[r] = l;
            l = acc[r][1] + bv.y; if (m.y) { float e = expf(l); s += e; t += e * l; } if (jb + 1 == aidx[r]) la_sm[r] = l;
            l = acc[r][2] + bv.z; if (m.z) { float e = expf(l); s += e; t += e * l; } if (jb + 2 == aidx[r]) la_sm[r] = l;
            l = acc[r][3] + bv.w; if (m.w) { float e = expf(l); s += e; t += e * l; } if (jb + 3 == aidx[r]) la_sm[r] = l;
#pragma unroll
            for (int o = 16; o > 0; o >>= 1) {
                s += __shfl_down_sync(0xffffffffu, s, o);
                t += __shfl_down_sync(0xffffffffu, t, o);
            }
            if (lane == 0) { redS[r][warp] = s; redT[r][warp] = t; }
        }
        __syncthreads();
        if (tid < 16) {
            double s = 0.0, t = 0.0;
#pragma unroll
            for (int w = 0; w < 8; w++) { s += (double)redS[tid][w]; t += (double)redT[tid][w]; }
            sRun[tid] += s; tRun[tid] += t;
        }
        __syncthreads();
    }
    if (tid < 16) {
        const int i = r0 + tid;
        double S = sRun[tid], T1 = tRun[tid];
        double lS = log(S);
        g_ent_pim[i] = T1 / S - lS;                      // sum_masked p*log p
        g_lg_pim[i]  = (float)((double)la_sm[tid] - lS); // log pim[i, a]
    }
}

// ------------------------------ vf broadcast (register-tiled) ----------------
__global__ __launch_bounds__(256) void vf_kernel(const float* __restrict__ ovp,
                                                 const float* __restrict__ ret)
{
    __shared__ float vp_s[8];
    __shared__ float part[8][257];
    const int tid = threadIdx.x, warp = tid >> 5, lane = tid & 31;
    const int r0 = blockIdx.x * 8;
    if (tid < 8) vp_s[tid] = g_vpred[r0 + tid];
    __syncthreads();

    float accr[8];
#pragma unroll
    for (int r = 0; r < 8; r++) accr[r] = 0.f;

#pragma unroll 1
    for (int c = 0; c < 4; c++) {
        const int j0 = c * 1024 + tid * 4;
        float4 rt4 = __ldg((const float4*)(ret + j0));
        float4 ov4 = __ldg((const float4*)(ovp + j0));
#pragma unroll
        for (int r = 0; r < 8; r++) {
            float vp = vp_s[r];
            float d, dc, t0, t1, t2, t3;
            d = vp - rt4.x; dc = ov4.x + fminf(fmaxf(vp - ov4.x, -CLIPF), CLIPF) - rt4.x; t0 = fmaxf(d*d, dc*dc);
            d = vp - rt4.y; dc = ov4.y + fminf(fmaxf(vp - ov4.y, -CLIPF), CLIPF) - rt4.y; t1 = fmaxf(d*d, dc*dc);
            d = vp - rt4.z; dc = ov4.z + fminf(fmaxf(vp - ov4.z, -CLIPF), CLIPF) - rt4.z; t2 = fmaxf(d*d, dc*dc);
            d = vp - rt4.w; dc = ov4.w + fminf(fmaxf(vp - ov4.w, -CLIPF), CLIPF) - rt4.w; t3 = fmaxf(d*d, dc*dc);
            accr[r] += (t0 + t1) + (t2 + t3);
        }
    }
#pragma unroll
    for (int r = 0; r < 8; r++) part[r][tid] = accr[r];
    __syncthreads();

    // warp w reduces row w (fixed order -> deterministic)
    double s = 0.0;
#pragma unroll
    for (int m = 0; m < 8; m++) s += (double)part[warp][m * 32 + lane];
#pragma unroll
    for (int o = 16; o > 0; o >>= 1) s += __shfl_down_sync(0xffffffffu, s, o);
    if (lane == 0) g_vf_row[r0 + warp] = s;
}

// ------------------------------ finalize ------------------------------------
__global__ __launch_bounds__(1024) void finalize_kernel(
    const float* __restrict__ GAE, const float* __restrict__ lgold, float* __restrict__ out)
{
    __shared__ double rA[1024], rB[1024];
    const int tid = threadIdx.x;
    double s1 = 0.0, s2 = 0.0;
    for (int i = tid; i < BT; i += 1024) { double g = GAE[i]; s1 += g; s2 += g * g; }
    rA[tid] = s1; rB[tid] = s2; __syncthreads();
    for (int o = 512; o > 0; o >>= 1) {
        if (tid < o) { rA[tid] += rA[tid + o]; rB[tid] += rB[tid + o]; }
        __syncthreads();
    }
    double mean = rA[0] / (double)BT;
    double var  = rB[0] / (double)BT - mean * mean;
    if (var < 0.0) var = 0.0;
    double denom = sqrt(var) + 1e-8;
    __syncthreads();

    double pg = 0.0, ent = 0.0, vf = 0.0;
    for (int i = tid; i < BT; i += 1024) {
        double g = ((double)GAE[i] - mean) / denom;
        float lgnew = ((i & 1) == 0) ? g_lg_pir[i] : g_lg_pim[i];
        double rt = exp((double)lgnew - (double)lgold[i]);
        double rtc = rt < (1.0 - CLIPF) ? (1.0 - CLIPF) : (rt > (1.0 + CLIPF) ? (1.0 + CLIPF) : rt);
        double p1 = -g * rt, p2 = -g * rtc;
        pg  += (p1 > p2) ? p1 : p2;
        ent += g_ent_pir[i] + g_ent_pim[i];
        vf  += g_vf_row[i];
    }
    rA[tid] = pg; rB[tid] = ent; __syncthreads();
    for (int o = 512; o > 0; o >>= 1) {
        if (tid < o) { rA[tid] += rA[tid + o]; rB[tid] += rB[tid + o]; }
        __syncthreads();
    }
    double pg_tot = rA[0], ent_tot = rB[0];
    __syncthreads();
    rA[tid] = vf; __syncthreads();
    for (int o = 512; o > 0; o >>= 1) {
        if (tid < o) rA[tid] += rA[tid + o];
        __syncthreads();
    }
    if (tid == 0) {
        double pg_loss = pg_tot / (double)BT;
        double entropy = -ent_tot;
        double vf_loss = 0.5 * rA[0] / ((double)BT * (double)BT);
        out[0] = (float)(pg_loss - entropy + vf_loss);
        out[1] = (float)pg_loss;
        out[2] = (float)entropy;
        out[3] = (float)vf_loss;
    }
}

// ------------------------------ launch --------------------------------------
extern "C" void kernel_launch(void* const* d_in, const int* in_sizes, int n_in,
                              void* d_out, int out_size) {
    const float* x      = (const float*)d_in[0];
    const int*   mask   = (const int*)  d_in[1];
    const float* lgold  = (const float*)d_in[2];
    const int*   ataken = (const int*)  d_in[3];
    const float* GAE    = (const float*)d_in[4];
    const float* ovp    = (const float*)d_in[5];
    const float* ret    = (const float*)d_in[6];
    const float* W1 = (const float*)d_in[7],  *b1 = (const float*)d_in[8];
    const float* W2 = (const float*)d_in[9],  *b2 = (const float*)d_in[10];
    const float* W3 = (const float*)d_in[11], *b3 = (const float*)d_in[12];
    const float* W4 = (const float*)d_in[13], *b4 = (const float*)d_in[14];
    const float* lk = (const float*)d_in[15];
    const float* lr = (const float*)d_in[16];
    const float* lb = (const float*)d_in[17];
    const float* pirW = (const float*)d_in[18], *pirb = (const float*)d_in[19];
    const float* pimW = (const float*)d_in[20], *pimb = (const float*)d_in[21];
    const float* vW   = (const float*)d_in[22], *vb   = (const float*)d_in[23];
    float* out = (float*)d_out;

    conv_kernel<<<512, 256>>>(x, W1, b1, W2, b2, W3, b3, W4, b4);
    xz_kernel<<<dim3(2, 512), 128>>>(lk, lb);
    lstm_kernel<<<128, 256>>>(lr);
    pir_v_kernel<<<512, 256>>>(pirW, pirb, vW, vb, ataken);
    pim_kernel<<<256, 256>>>(pimW, pimb, mask, ataken);
    vf_kernel<<<512, 256>>>(ovp, ret);
    finalize_kernel<<<1, 1024>>>(GAE, lgold, out);
}